// round 9
// baseline (speedup 1.0000x reference)
#include <cuda_runtime.h>
#include <math.h>

#define NN 100000
#define NE 1200000
#define KP1 4096
#define KP2 256
#define NCH 98            // ceil(NN/1024)
#define SLOPE 0.01f
#define EC 65536          // filtered-edge capacity (expected ~2000)

// ---------------- scratch (~7 MB total; no allocations) ----------------
__device__ double   g_ddinv[NN];           // conv1 dinv (double; also degree accum)
__device__ double   g_dagg3[NN * 3];       // conv1 pos aggregation (double)
                                           // reused later: x2[4096*128] floats (2MB <= 2.4MB)
__device__ unsigned g_keys1[NN];
__device__ int      g_inv1[NN];
__device__ float    g_B[524288];           // phase1 = [x1p | agg64]; phase2 = agg128[4096*128]

#define G_X2     ((float*)g_dagg3)         /* [KP1*128] float, after dagg3 dead */
#define G_X1P    (g_B)                     /* [KP1*64]  */
#define G_AGG64  (g_B + 262144)            /* [KP1*64]  */
#define G_AGG128 (g_B)                     /* [KP1*128] */

__device__ unsigned g_hist[256];
__device__ unsigned g_prefix;
__device__ int      g_kst;
__device__ int      g_cg[NCH], g_ce[NCH], g_ceOff[NCH], g_keptOff[NCH];
__device__ int      g_sel1[KP1];
__device__ int      g_sel1s[KP1];
__device__ unsigned long long g_ck[KP1];   // reused: pool1 keys then pool2 keys
__device__ int      g_rank[KP1];           // reused: pool1 ranks then pool2 ranks
__device__ int2     g_edge[EC];
__device__ int      g_ne1;
__device__ float    g_dinv2[KP1];          // phase1: float deg2 accumulator
__device__ float    g_sc2[KP1];
__device__ int      g_win[KP2];
__device__ float    g_xflat[256 * 256];
__device__ float    g_invp1;
__device__ double   g_invp2d;

__device__ __forceinline__ float leaky(float v) { return v > 0.f ? v : SLOPE * v; }
__device__ __forceinline__ unsigned fkey(float f) {
    unsigned u = __float_as_uint(f);
    return (u & 0x80000000u) ? ~u : (u | 0x80000000u);
}
__device__ __forceinline__ float ikey(unsigned k) {   // exact inverse of fkey
    return __uint_as_float((k & 0x80000000u) ? (k ^ 0x80000000u) : ~k);
}

// ---------------- init / zero ----------------
__global__ void k_init(const float* __restrict__ p1, const float* __restrict__ p2) {
    int t = threadIdx.x;              // 256
    g_hist[t] = 0;
    if (t == 0) {
        g_prefix = 0; g_kst = KP1; g_ne1 = 0;
        double s = 0.0;
        for (int i = 0; i < 64; i++) { double v = (double)p1[i]; s += v * v; }
        g_invp1 = (float)(1.0 / sqrt(s));
        double s2 = 0.0;
        for (int i = 0; i < 256; i++) { double v = (double)p2[i]; s2 += v * v; }
        g_invp2d = 1.0 / sqrt(s2);
    }
}
__global__ void k_zpre() {
    int i0 = blockIdx.x * blockDim.x + threadIdx.x, st = gridDim.x * blockDim.x;
    for (int i = i0; i < NN; i += st) g_ddinv[i] = 0.0;
    for (int i = i0; i < NN * 3; i += st) g_dagg3[i] = 0.0;
    for (int i = i0; i < KP1; i += st) g_dinv2[i] = 0.f;
}
__global__ void k_zagg64() {          // zero B[262144:524288)
    for (int i = blockIdx.x * blockDim.x + threadIdx.x; i < 262144; i += gridDim.x * blockDim.x)
        g_B[262144 + i] = 0.f;
}
__global__ void k_zB() {              // zero all of B (for agg128)
    for (int i = blockIdx.x * blockDim.x + threadIdx.x; i < 524288; i += gridDim.x * blockDim.x)
        g_B[i] = 0.f;
}

// ---------------- conv1: degree, dinv, pos aggregation (double) ----------------
__global__ void k_deg(const int* __restrict__ dst) {
    int e = blockIdx.x * blockDim.x + threadIdx.x;
    if (e < NE) atomicAdd(&g_ddinv[dst[e]], 1.0);
}
__global__ void k_dinv() {
    int i = blockIdx.x * blockDim.x + threadIdx.x;
    if (i < NN) g_ddinv[i] = 1.0 / sqrt(g_ddinv[i] + 1.0);
}
__global__ void k_agg3(const int* __restrict__ src, const int* __restrict__ dst,
                       const float* __restrict__ pos) {
    int e = blockIdx.x * blockDim.x + threadIdx.x;
    if (e >= NE) return;
    int s = src[e], d = dst[e];
    double nm = g_ddinv[s] * g_ddinv[d];
    atomicAdd(&g_dagg3[d * 3 + 0], (double)pos[s * 3 + 0] * nm);
    atomicAdd(&g_dagg3[d * 3 + 1], (double)pos[s * 3 + 1] * nm);
    atomicAdd(&g_dagg3[d * 3 + 2], (double)pos[s * 3 + 2] * nm);
}

// ---------------- score1 (float dot on double-derived inputs) ----------------
__global__ void k_score1(const float* __restrict__ pos, const float* __restrict__ W1,
                         const float* __restrict__ b1, const float* __restrict__ p1) {
    __shared__ float sW[192], sb[64], sp[64];
    int t = threadIdx.x;   // 128
    for (int i = t; i < 192; i += 128) sW[i] = W1[i];
    if (t < 64) { sb[t] = b1[t]; sp[t] = p1[t]; }
    __syncthreads();
    int i = blockIdx.x * blockDim.x + t;
    if (i >= NN) return;
    double dd = g_ddinv[i], d2 = dd * dd;
    float c0 = (float)(g_dagg3[3 * i + 0] + (double)pos[3 * i + 0] * d2);
    float c1 = (float)(g_dagg3[3 * i + 1] + (double)pos[3 * i + 1] * d2);
    float c2 = (float)(g_dagg3[3 * i + 2] + (double)pos[3 * i + 2] * d2);
    float s = 0.f;
#pragma unroll
    for (int f = 0; f < 64; f++) {
        float v = sb[f] + c0 * sW[f] + c1 * sW[64 + f] + c2 * sW[128 + f];
        s += leaky(v) * sp[f];
    }
    g_keys1[i] = fkey(tanhf(s * g_invp1));
}

// ---------------- radix select (top KP1 of NN keys) ----------------
__global__ void k_hist(int shift, int round) {
    __shared__ unsigned sh[256];
    int t = threadIdx.x;
    sh[t] = 0;
    __syncthreads();
    int i = blockIdx.x * blockDim.x + t;
    if (i < NN) {
        unsigned key = g_keys1[i];
        bool m = (round == 0) || ((key >> (shift + 8)) == g_prefix);
        if (m) atomicAdd(&sh[(key >> shift) & 255u], 1u);
    }
    __syncthreads();
    if (sh[t]) atomicAdd(&g_hist[t], sh[t]);
}
__global__ void k_select() {
    if (threadIdx.x == 0) {
        int k = g_kst;
        unsigned cum = 0; int sel = 0; int kk = k;
        for (int b = 255; b >= 0; b--) {
            unsigned c = g_hist[b];
            if (cum + c >= (unsigned)k) { sel = b; kk = k - (int)cum; break; }
            cum += c;
        }
        g_prefix = (g_prefix << 8) | (unsigned)sel;
        g_kst = kk;
    }
    __syncthreads();
    g_hist[threadIdx.x] = 0;
}

// ---------------- pool1: kept-set compaction (index order) ----------------
__global__ void k_poolcnt() {
    int c = blockIdx.x, t = threadIdx.x;
    int i = c * 1024 + t;
    int gt = 0, eq = 0;
    unsigned th = g_prefix;
    if (i < NN) { unsigned k = g_keys1[i]; gt = (k > th); eq = (k == th); }
    __shared__ int sg, se;
    if (t == 0) { sg = 0; se = 0; }
    __syncthreads();
    unsigned bg = __ballot_sync(0xffffffffu, gt);
    unsigned be = __ballot_sync(0xffffffffu, eq);
    if ((t & 31) == 0) { atomicAdd(&sg, __popc(bg)); atomicAdd(&se, __popc(be)); }
    __syncthreads();
    if (t == 0) { g_cg[c] = sg; g_ce[c] = se; }
}
__global__ void k_scanchunks() {
    if (threadIdx.x == 0) {
        int T = g_kst;
        int ceo = 0, ko = 0;
        for (int c = 0; c < NCH; c++) {
            g_ceOff[c] = ceo;
            int take = T - ceo; if (take < 0) take = 0; if (take > g_ce[c]) take = g_ce[c];
            g_keptOff[c] = ko;
            ko += g_cg[c] + take;
            ceo += g_ce[c];
        }
    }
}
__global__ void k_assign() {
    int c = blockIdx.x, t = threadIdx.x;
    int i = c * 1024 + t;
    unsigned th = g_prefix; int T = g_kst;
    int gt = 0, eq = 0;
    if (i < NN) { unsigned k = g_keys1[i]; gt = (k > th); eq = (k == th); }
    __shared__ int sw[32], swo[32];
    int lane = t & 31, wid = t >> 5;
    unsigned be = __ballot_sync(0xffffffffu, eq);
    int eqr = __popc(be & ((1u << lane) - 1u));
    if (lane == 0) sw[wid] = __popc(be);
    __syncthreads();
    if (t == 0) { int s = 0; for (int w = 0; w < 32; w++) { swo[w] = s; s += sw[w]; } }
    __syncthreads();
    eqr += swo[wid];
    int kept = gt || (eq && (g_ceOff[c] + eqr) < T);
    __syncthreads();
    unsigned bk = __ballot_sync(0xffffffffu, kept);
    int kr = __popc(bk & ((1u << lane) - 1u));
    if (lane == 0) sw[wid] = __popc(bk);
    __syncthreads();
    if (t == 0) { int s = 0; for (int w = 0; w < 32; w++) { swo[w] = s; s += sw[w]; } }
    __syncthreads();
    kr += swo[wid];
    if (i < NN) {
        if (kept) { int id = g_keptOff[c] + kr; g_sel1[id] = i; }
        g_inv1[i] = -1;
    }
}

// ---------------- pool1 exact reference order: rank by (score desc, idx asc) ----------------
__global__ void k_ck1() {
    int id = blockIdx.x * blockDim.x + threadIdx.x;
    if (id >= KP1) return;
    int v = g_sel1[id];
    g_ck[id] = ((unsigned long long)g_keys1[v] << 32) | (unsigned)(0xFFFFFFFFu - (unsigned)v);
    g_rank[id] = 0;
}
__global__ void k_rank() {            // used for pool1 AND pool2 ranking
    int it = blockIdx.x & 15, jt = blockIdx.x >> 4;
    __shared__ unsigned long long sj[256];
    int t = threadIdx.x;
    sj[t] = g_ck[jt * 256 + t];
    __syncthreads();
    unsigned long long ki = g_ck[it * 256 + t];
    int cnt = 0;
#pragma unroll 8
    for (int j = 0; j < 256; j++) cnt += (sj[j] > ki);
    if (cnt) atomicAdd(&g_rank[it * 256 + t], cnt);
}
__global__ void k_perm1() {
    int id = blockIdx.x * blockDim.x + threadIdx.x;
    if (id >= KP1) return;
    int v = g_sel1[id];
    int r = g_rank[id];
    g_sel1s[r] = v;
    g_inv1[v] = r;
}

// ---------------- x1p rows for kept nodes (score recovered from key) ----------------
__global__ void k_x1p(const float* __restrict__ pos, const float* __restrict__ W1,
                      const float* __restrict__ b1) {
    int id = blockIdx.x;       // slot in reference order
    int f = threadIdx.x;       // 64
    __shared__ float sc[4];
    int v = g_sel1s[id];
    if (f < 3) {
        double dd = g_ddinv[v];
        sc[f] = (float)(g_dagg3[3 * v + f] + (double)pos[3 * v + f] * dd * dd);
    }
    if (f == 3) sc[3] = ikey(g_keys1[v]);
    __syncthreads();
    float val = b1[f] + sc[0] * W1[f] + sc[1] * W1[64 + f] + sc[2] * W1[128 + f];
    G_X1P[id * 64 + f] = leaky(val) * sc[3];
}

// ---------------- surviving edges + deg2 ----------------
__global__ void k_filter(const int* __restrict__ src, const int* __restrict__ dst) {
    int e = blockIdx.x * blockDim.x + threadIdx.x;
    if (e >= NE) return;
    int ms = g_inv1[src[e]];
    int md = g_inv1[dst[e]];
    if (ms >= 0 && md >= 0) {
        int p = atomicAdd(&g_ne1, 1);
        if (p < EC) g_edge[p] = make_int2(ms, md);
        atomicAdd(&g_dinv2[md], 1.0f);
    }
}
__global__ void k_dinv2() {
    int i = blockIdx.x * blockDim.x + threadIdx.x;
    if (i < KP1) g_dinv2[i] = 1.0f / sqrtf(g_dinv2[i] + 1.0f);
}

// ---------------- conv2/conv3 edge aggregation ----------------
__global__ void k_agg64() {
    int ne = g_ne1; if (ne > EC) ne = EC;
    int tot = ne * 64;
    for (int idx = blockIdx.x * blockDim.x + threadIdx.x; idx < tot; idx += gridDim.x * blockDim.x) {
        int e = idx >> 6, f = idx & 63;
        int2 ed = g_edge[e];
        float nm = g_dinv2[ed.x] * g_dinv2[ed.y];
        atomicAdd(&G_AGG64[ed.y * 64 + f], G_X1P[ed.x * 64 + f] * nm);
    }
}
__global__ void k_agg128() {
    int ne = g_ne1; if (ne > EC) ne = EC;
    int tot = ne * 128;
    for (int idx = blockIdx.x * blockDim.x + threadIdx.x; idx < tot; idx += gridDim.x * blockDim.x) {
        int e = idx >> 7, f = idx & 127;
        int2 ed = g_edge[e];
        float nm = g_dinv2[ed.x] * g_dinv2[ed.y];
        atomicAdd(&G_AGG128[ed.y * 128 + f], G_X2[ed.x * 128 + f] * nm);
    }
}

// ---------------- x2 = leaky((agg64 + x1p*d2)@W2 + b2): 16 nodes/block ----------------
__global__ void k_x2(const float* __restrict__ W2, const float* __restrict__ b2) {
    __shared__ float sW[64 * 128];
    __shared__ float sh[16 * 64];
    __shared__ float sb[128];
    int t = threadIdx.x;   // 128
    for (int i = t; i < 64 * 128; i += 128) sW[i] = W2[i];
    sb[t] = b2[t];
    int n0 = blockIdx.x * 16;
    for (int i = t; i < 16 * 64; i += 128) {
        int n = i >> 6, c = i & 63;
        int node = n0 + n;
        float d = g_dinv2[node];
        sh[i] = G_AGG64[node * 64 + c] + G_X1P[node * 64 + c] * d * d;
    }
    __syncthreads();
    for (int n = 0; n < 16; n++) {
        float acc = sb[t];
#pragma unroll
        for (int c = 0; c < 64; c++) acc += sh[n * 64 + c] * sW[c * 128 + t];
        G_X2[(n0 + n) * 128 + t] = leaky(acc);
    }
}

// ---------------- fused x3 + score2: shared sx3 + warp-per-node score ----------------
__global__ void k_x3s(const float* __restrict__ W3, const float* __restrict__ b3,
                      const float* __restrict__ p2) {
    __shared__ float sW[128 * 64];      // 32 KB
    __shared__ float sh[8 * 128];       // 4 KB
    __shared__ float sx3[8 * 256];      // 8 KB
    __shared__ float sb[256], sp[256];  // 2 KB
    int t = threadIdx.x;   // 256
    sb[t] = b3[t]; sp[t] = p2[t];
    int n0 = blockIdx.x * 8;
    for (int i = t; i < 8 * 128; i += 256) {
        int n = i >> 7, c = i & 127;
        int node = n0 + n;
        float d = g_dinv2[node];
        sh[i] = G_AGG128[node * 128 + c] + G_X2[node * 128 + c] * d * d;
    }
    int cc = t & 63;
    int ng = t >> 6;                 // 0..3 -> nodes ng*2, ng*2+1
    for (int tile = 0; tile < 4; tile++) {
        __syncthreads();
        for (int i = t; i < 128 * 64; i += 256) {
            int c = i >> 6, w = i & 63;
            sW[i] = W3[c * 256 + tile * 64 + w];
        }
        __syncthreads();
        int col = tile * 64 + cc;
        float bb = sb[col];
#pragma unroll
        for (int g = 0; g < 2; g++) {
            int n = ng * 2 + g;
            float acc = bb;
#pragma unroll
            for (int c = 0; c < 128; c++) acc += sh[n * 128 + c] * sW[c * 64 + cc];
            sx3[n * 256 + col] = leaky(acc);
        }
    }
    __syncthreads();
    // score: warp w handles node w (8 warps, 8 nodes)
    int w = t >> 5, lane = t & 31;
    double s = 0.0;
    for (int c = lane; c < 256; c += 32) s += (double)sx3[w * 256 + c] * (double)sp[c];
#pragma unroll
    for (int o = 16; o > 0; o >>= 1) s += __shfl_down_sync(0xffffffffu, s, o);
    if (lane == 0) {
        int node = n0 + w;
        float sc = tanhf((float)(s * g_invp2d));
        g_sc2[node] = sc;
        g_ck[node] = ((unsigned long long)fkey(sc) << 32) | (unsigned)(0xFFFFFFFFu - (unsigned)node);
        g_rank[node] = 0;
    }
}

// ---------------- winners + gather (recompute x3 rows for 256 winners) ----------------
__global__ void k_win() {
    int i = blockIdx.x * blockDim.x + threadIdx.x;
    if (i < KP1) { int r = g_rank[i]; if (r < KP2) g_win[r] = i; }
}
__global__ void k_gather(const float* __restrict__ W3, const float* __restrict__ b3) {
    __shared__ float sh[128];
    __shared__ float ssc;
    int r = blockIdx.x;     // winner rank 0..255
    int c = threadIdx.x;    // 256 cols
    int i = g_win[r];
    if (c < 128) {
        float d = g_dinv2[i];
        sh[c] = G_AGG128[i * 128 + c] + G_X2[i * 128 + c] * d * d;
    }
    if (c == 128) ssc = g_sc2[i];
    __syncthreads();
    float acc = b3[c];
#pragma unroll 8
    for (int k = 0; k < 128; k++) acc += sh[k] * W3[k * 256 + c];
    g_xflat[c * 256 + r] = leaky(acc) * ssc;
}

// ---------------- FC ----------------
__global__ void k_outinit(const float* __restrict__ fcb, float* __restrict__ out) {
    out[threadIdx.x] = fcb[threadIdx.x];
}
__global__ void k_fc(const float* __restrict__ W, float* __restrict__ out) {
    int t = threadIdx.x;         // 128 threads x float4 cols
    int row0 = blockIdx.x * 64;  // 1024 blocks
    const float4* W4 = (const float4*)W;
    float4 acc = make_float4(0.f, 0.f, 0.f, 0.f);
#pragma unroll 4
    for (int r = 0; r < 64; r++) {
        int row = row0 + r;
        float v = g_xflat[row];
        float4 w = __ldg(&W4[(size_t)row * 128 + t]);
        acc.x += v * w.x; acc.y += v * w.y; acc.z += v * w.z; acc.w += v * w.w;
    }
    atomicAdd(&out[t * 4 + 0], acc.x);
    atomicAdd(&out[t * 4 + 1], acc.y);
    atomicAdd(&out[t * 4 + 2], acc.z);
    atomicAdd(&out[t * 4 + 3], acc.w);
}

// ---------------- launch ----------------
extern "C" void kernel_launch(void* const* d_in, const int* in_sizes, int n_in,
                              void* d_out, int out_size) {
    const float* pos = (const float*)d_in[0];
    const int*   ei  = (const int*)d_in[1];      // JAX x64 disabled -> int32
    const float* W1  = (const float*)d_in[2];
    const float* b1  = (const float*)d_in[3];
    const float* W2  = (const float*)d_in[4];
    const float* b2  = (const float*)d_in[5];
    const float* W3  = (const float*)d_in[6];
    const float* b3  = (const float*)d_in[7];
    const float* p1  = (const float*)d_in[8];
    const float* p2  = (const float*)d_in[9];
    const float* fcW = (const float*)d_in[10];
    const float* fcb = (const float*)d_in[11];
    float* out = (float*)d_out;
    (void)n_in; (void)in_sizes; (void)out_size;

    const int* src = ei;
    const int* dst = ei + NE;
    int eg = (NE + 255) / 256;
    int hg = (NN + 255) / 256;

    k_init<<<1, 256>>>(p1, p2);
    k_zpre<<<256, 256>>>();

    // conv1 (aggregate 3-dim pos before matmul; double precision)
    k_deg<<<eg, 256>>>(dst);
    k_dinv<<<hg, 256>>>();
    k_agg3<<<eg, 256>>>(src, dst, pos);
    k_score1<<<(NN + 127) / 128, 128>>>(pos, W1, b1, p1);

    // radix select top-KP1
    k_hist<<<hg, 256>>>(24, 0); k_select<<<1, 256>>>();
    k_hist<<<hg, 256>>>(16, 1); k_select<<<1, 256>>>();
    k_hist<<<hg, 256>>>(8, 2);  k_select<<<1, 256>>>();
    k_hist<<<hg, 256>>>(0, 3);  k_select<<<1, 256>>>();

    // pool1 compaction + exact reference ordering
    k_poolcnt<<<NCH, 1024>>>();
    k_scanchunks<<<1, 32>>>();
    k_assign<<<NCH, 1024>>>();
    k_ck1<<<KP1 / 256, 256>>>();
    k_rank<<<256, 256>>>();
    k_perm1<<<KP1 / 256, 256>>>();

    // pooled features + surviving edges
    k_x1p<<<KP1, 64>>>(pos, W1, b1);
    k_zagg64<<<128, 256>>>();
    k_filter<<<eg, 256>>>(src, dst);
    k_dinv2<<<(KP1 + 255) / 256, 256>>>();

    // conv2 (x2 overwrites dagg3 region; dagg3 dead after k_x1p)
    k_agg64<<<256, 256>>>();
    k_x2<<<KP1 / 16, 128>>>(W2, b2);

    // conv3 (agg128 overwrites arena B after x2 consumed it)
    k_zB<<<256, 256>>>();
    k_agg128<<<256, 256>>>();

    // pool2: fused x3+score, exact stable ranks, winner gather
    k_x3s<<<KP1 / 8, 256>>>(W3, b3, p2);
    k_rank<<<256, 256>>>();
    k_win<<<KP1 / 256, 256>>>();
    k_gather<<<KP2, 256>>>(W3, b3);

    // FC
    k_outinit<<<1, 512>>>(fcb, out);
    k_fc<<<1024, 128>>>(fcW, out);
}